// round 5
// baseline (speedup 1.0000x reference)
#include <cuda_runtime.h>
#include <cuda_bf16.h>

// Scratch (allocation-free rule: __device__ globals)
__device__ float g_SC[1024];               // S_C[k*4+l]

// ---------------------------------------------------------------------------
// Kernel 1: full reduce of C over (i,j) -> g_SC. 128 blocks x 192 threads.
// Block cid owns float4-cols {2cid, 2cid+1}; per-thread 32 rows (stride 96),
// smem tree over the 96 row-groups.
// ---------------------------------------------------------------------------
__global__ void sumC_kernel(const float* __restrict__ C) {
    __shared__ float4 sm4[192];            // [c(2)][rg(96)]
    const int t   = threadIdx.x;           // 0..191
    const int cid = blockIdx.x;
    const int c   = t & 1;
    const int rg  = t >> 1;                // 0..95
    const int c4  = 2 * cid + c;
    const float4* __restrict__ C4 = (const float4*)C;   // 256 f4 per row
    float4 acc = make_float4(0.f, 0.f, 0.f, 0.f);
#pragma unroll 8
    for (int q = 0; q < 32; ++q) {
        float4 v = C4[(rg + 96 * q) * 256 + c4];
        acc.x += v.x; acc.y += v.y; acc.z += v.z; acc.w += v.w;
    }
    sm4[c * 96 + rg] = acc;
    __syncthreads();
    for (int s = 48; s >= 3; s >>= 1) {
        if (rg < s) {
            float4 a  = sm4[c * 96 + rg];
            float4 bv = sm4[c * 96 + rg + s];
            a.x += bv.x; a.y += bv.y; a.z += bv.z; a.w += bv.w;
            sm4[c * 96 + rg] = a;
        }
        __syncthreads();
    }
    if (rg == 0) {
        float4 a0 = sm4[c * 96 + 0];
        float4 a1 = sm4[c * 96 + 1];
        float4 a2 = sm4[c * 96 + 2];
        float4 r;
        r.x = a0.x + a1.x + a2.x;
        r.y = a0.y + a1.y + a2.y;
        r.z = a0.z + a1.z + a2.z;
        r.w = a0.w + a1.w + a2.w;
        ((float4*)g_SC)[2 * cid + c] = r;
    }
}

// ---------------------------------------------------------------------------
// Kernel 2 (fused per-batch): block b reads image x[b] (786 KB), computes all
// 64 bins S_x[b][h1][w2] in smem, then stores out[b] = S_C[kl] * S_x[hw]
// (262 KB) directly. Stores from finished blocks overlap reads of running
// blocks -> DRAM pipe never idles.
//
// 768 threads = 4 h1-groups x 192 float4-cols; each thread accumulates TWO
// bins (h1a = t/192 and h1b = h1a+4) over 32 rows each (row = h1 + 8q).
// Bin-safe smem tree (strides multiple of 24 floats preserve w2).
// ---------------------------------------------------------------------------
__global__ void fused_kernel(const float* __restrict__ x,
                             float* __restrict__ out) {
    __shared__ float sm[8 * 768];          // [h1][768]
    __shared__ float sx_s[64];             // S_x[h1*8+w2]
    __shared__ float sc_s[1024];           // S_C copy

    const int t   = threadIdx.x;           // 0..767
    const int b   = blockIdx.x;            // 0..127
    const int c4  = t % 192;
    const int h1a = t / 192;               // 0..3
    const int h1b = h1a + 4;

    const float4* __restrict__ x4 = (const float4*)x;
    const long base = (long)b * 49152 + c4;          // + row*192

    float4 accA = make_float4(0.f, 0.f, 0.f, 0.f);
    float4 accB = make_float4(0.f, 0.f, 0.f, 0.f);
#pragma unroll 4
    for (int q = 0; q < 32; ++q) {
        float4 va = x4[base + (long)(h1a + 8 * q) * 192];
        float4 vb = x4[base + (long)(h1b + 8 * q) * 192];
        accA.x += va.x; accA.y += va.y; accA.z += va.z; accA.w += va.w;
        accB.x += vb.x; accB.y += vb.y; accB.z += vb.z; accB.w += vb.w;
    }
    ((float4*)sm)[h1a * 192 + c4] = accA;
    ((float4*)sm)[h1b * 192 + c4] = accB;

    // stage S_C while the reduce settles
    if (t < 512) { sc_s[t] = g_SC[t]; sc_s[t + 512] = g_SC[t + 512]; }
    __syncthreads();

    // per-h1 tree reduce: 8 groups x 96 threads; strides 384/192/96/48/24
    {
        const int g  = t / 96;             // 0..7
        const int tg = t % 96;
        float* s = sm + g * 768;
#pragma unroll
        for (int i = 0; i < 4; ++i) s[tg + 96 * i] += s[tg + 96 * i + 384];
        __syncthreads();
        s[tg] += s[tg + 192];
        s[tg + 96] += s[tg + 96 + 192];
        __syncthreads();
        s[tg] += s[tg + 96];
        __syncthreads();
        if (tg < 48) s[tg] += s[tg + 48];
        __syncthreads();
        if (tg < 24) s[tg] += s[tg + 24];
        __syncthreads();
        if (tg < 8)
            sx_s[g * 8 + tg] = s[3 * tg] + s[3 * tg + 1] + s[3 * tg + 2];
    }
    __syncthreads();

    // expand: out[b, kl, hw] = sc[kl] * sx[hw]; 16384 float4, coalesced
    const float4* sx4 = (const float4*)sx_s;         // 16 entries
    float4* out4 = (float4*)out + (long)b * 16384;
    for (int j = t; j < 16384; j += 768) {
        const float  sc = sc_s[j >> 4];
        const float4 sx = sx4[j & 15];
        float4 r;
        r.x = sc * sx.x; r.y = sc * sx.y; r.z = sc * sx.z; r.w = sc * sx.w;
        out4[j] = r;
    }
}

// ---------------------------------------------------------------------------
extern "C" void kernel_launch(void* const* d_in, const int* in_sizes, int n_in,
                              void* d_out, int out_size) {
    const float* x = (const float*)d_in[0];  // [128,256,256,3]
    const float* C = (const float*)d_in[1];  // [768,4,256,4]
    float* out = (float*)d_out;              // [128,256,4,8,8]

    sumC_kernel<<<128, 192>>>(C);
    fused_kernel<<<128, 768>>>(x, out);
}

// round 6
// speedup vs baseline: 1.1623x; 1.1623x over previous
#include <cuda_runtime.h>
#include <cuda_bf16.h>

// Scratch (allocation-free rule: __device__ globals)
__device__ float g_SC[1024];       // S_C[k*4+l]
__device__ float g_SX[128 * 64];   // S_x[b*64 + h1*8 + w2]
__device__ int   g_cnt[128];       // per-b producer completion count (0..4)
__device__ int   g_cntC;           // sumC completion count (0..128)

// ---------------------------------------------------------------------------
// Init: zero the dataflow counters (must happen every launch/replay).
// ---------------------------------------------------------------------------
__global__ void init_kernel() {
    const int t = threadIdx.x;
    if (t < 128) g_cnt[t] = 0;
    if (t == 128) g_cntC = 0;
}

// ---------------------------------------------------------------------------
// Main kernel: 640 blocks x 192 threads, ALL resident in one wave.
//   blocks [0,128):   sumC -> g_SC, then atomicAdd(g_cntC).
//   blocks [128,640): producer+consumer for (b = i/4, quarter = i%4):
//     produce: bins h1 in {quarter, quarter+4} of S_x[b] (exact, 2x32 rows,
//              bin-safe smem tree: strides multiple of 24 floats keep w2).
//     publish: threadfence + atomicAdd(g_cnt[b]).
//     consume: t0 spins until cnt[b]==4 && cntC==128, then block expands
//              out[b, quarter*256 .. +256, :] = S_C[kl] * S_x[b,hw].
//   Expand stores overlap other blocks' DRAM reads -> DRAM never idles.
// ---------------------------------------------------------------------------
__global__ void __launch_bounds__(192) main_kernel(const float* __restrict__ x,
                                                   const float* __restrict__ C,
                                                   float* __restrict__ out) {
    __shared__ float sm[1536];
    const int t = threadIdx.x;             // 0..191

    if (blockIdx.x < 128) {
        // ---------------- sumC ----------------
        float4* sm4 = (float4*)sm;         // [c(2)][rg(96)]
        const int cid = blockIdx.x;
        const int c  = t & 1;
        const int rg = t >> 1;             // 0..95
        const int c4 = 2 * cid + c;
        const float4* __restrict__ C4 = (const float4*)C;   // 256 f4/row
        float4 acc = make_float4(0.f, 0.f, 0.f, 0.f);
#pragma unroll 8
        for (int q = 0; q < 32; ++q) {
            float4 v = C4[(rg + 96 * q) * 256 + c4];
            acc.x += v.x; acc.y += v.y; acc.z += v.z; acc.w += v.w;
        }
        sm4[c * 96 + rg] = acc;
        __syncthreads();
        for (int s = 48; s >= 3; s >>= 1) {
            if (rg < s) {
                float4 a  = sm4[c * 96 + rg];
                float4 bv = sm4[c * 96 + rg + s];
                a.x += bv.x; a.y += bv.y; a.z += bv.z; a.w += bv.w;
                sm4[c * 96 + rg] = a;
            }
            __syncthreads();
        }
        if (rg == 0) {
            float4 a0 = sm4[c * 96 + 0];
            float4 a1 = sm4[c * 96 + 1];
            float4 a2 = sm4[c * 96 + 2];
            float4 r;
            r.x = a0.x + a1.x + a2.x;
            r.y = a0.y + a1.y + a2.y;
            r.z = a0.z + a1.z + a2.z;
            r.w = a0.w + a1.w + a2.w;
            ((float4*)g_SC)[2 * cid + c] = r;
        }
        __threadfence();
        __syncthreads();
        if (t == 0) atomicAdd(&g_cntC, 1);
        return;
    }

    // ---------------- producer: (b, quarter) ----------------
    const int idx     = blockIdx.x - 128;  // 0..511
    const int b       = idx >> 2;
    const int quarter = idx & 3;           // h1a = quarter, h1b = quarter+4

    const float4* __restrict__ x4 = (const float4*)x;   // 192 f4 per row
    const long base = (long)b * 49152 + t;

    float4 aA = make_float4(0.f, 0.f, 0.f, 0.f);
    float4 aB = make_float4(0.f, 0.f, 0.f, 0.f);
#pragma unroll 4
    for (int q = 0; q < 32; ++q) {
        float4 va = x4[base + (long)(quarter     + 8 * q) * 192];
        float4 vb = x4[base + (long)(quarter + 4 + 8 * q) * 192];
        aA.x += va.x; aA.y += va.y; aA.z += va.z; aA.w += va.w;
        aB.x += vb.x; aB.y += vb.y; aB.z += vb.z; aB.w += vb.w;
    }
    ((float4*)sm)[t]       = aA;           // bin A in sm[0..767]
    ((float4*)sm)[192 + t] = aB;           // bin B in sm[768..1535]
    __syncthreads();

    // Bin-safe tree reduce, both bins in parallel (g = bin, tg = 0..95)
    {
        const int g  = t / 96;
        const int tg = t % 96;
        float* s = sm + g * 768;
#pragma unroll
        for (int i = 0; i < 4; ++i) s[tg + 96 * i] += s[tg + 96 * i + 384];
        __syncthreads();
        s[tg]      += s[tg + 192];
        s[tg + 96] += s[tg + 96 + 192];
        __syncthreads();
        s[tg] += s[tg + 96];
        __syncthreads();
        if (tg < 48) s[tg] += s[tg + 48];
        __syncthreads();
        if (tg < 24) s[tg] += s[tg + 24];
        __syncthreads();
        if (tg < 8)
            g_SX[b * 64 + (quarter + 4 * g) * 8 + tg] =
                s[3 * tg] + s[3 * tg + 1] + s[3 * tg + 2];
    }
    __threadfence();
    __syncthreads();
    if (t == 0) atomicAdd(&g_cnt[b], 1);

    // ---------------- consume: wait for b complete + sumC complete --------
    if (t == 0) {
        while (atomicAdd(&g_cnt[b], 0) < 4)   __nanosleep(64);
        while (atomicAdd(&g_cntC, 0) < 128)   __nanosleep(64);
        __threadfence();
    }
    __syncthreads();

    // Stage scales: sc_s = sm[0..255] (this quarter's 256 kl), sx in sm[256..319]
    for (int i = t; i < 256; i += 192) sm[i] = g_SC[quarter * 256 + i];
    if (t < 16)
        ((float4*)(sm + 256))[t] = ((const float4*)g_SX)[b * 16 + t];
    __syncthreads();

    // Expand this quarter: 4096 float4, coalesced
    const float4* sx4 = (const float4*)(sm + 256);
    float4* out4 = (float4*)out + (long)b * 16384 + quarter * 4096;
    for (int j = t; j < 4096; j += 192) {
        const float  sc = sm[j >> 4];      // kl_local = j/16
        const float4 sx = sx4[j & 15];
        float4 r;
        r.x = sc * sx.x; r.y = sc * sx.y; r.z = sc * sx.z; r.w = sc * sx.w;
        out4[j] = r;
    }
}

// ---------------------------------------------------------------------------
extern "C" void kernel_launch(void* const* d_in, const int* in_sizes, int n_in,
                              void* d_out, int out_size) {
    const float* x = (const float*)d_in[0];  // [128,256,256,3]
    const float* C = (const float*)d_in[1];  // [768,4,256,4]
    float* out = (float*)d_out;              // [128,256,4,8,8]

    init_kernel<<<1, 192>>>();
    main_kernel<<<640, 192>>>(x, C, out);
}